// round 1
// baseline (speedup 1.0000x reference)
#include <cuda_runtime.h>
#include <math.h>

// Problem constants (fixed shapes from reference)
#define TT    2048          // B*S tokens
#define DDIM  1024          // model dim
#define HDIM  2048          // expert hidden
#define H2    (2*HDIM)      // 4096
#define NE    8             // experts
#define NK    2             // top-k
#define NSLOT (TT*NK)       // 4096 (every token appears exactly K times)

// ---------------- device scratch (static globals; no allocation) ----------
__device__ float g_h12[NSLOT * H2];        // 64 MB   pre-activation [slot, 2H]
__device__ float g_hidden[NSLOT * HDIM];   // 32 MB   swiglu output  [slot, H]
__device__ float g_y[NSLOT * DDIM];        // 16 MB   per-slot expert out [slot, D]
__device__ int   g_topk_idx[TT][NK];
__device__ float g_topk_w[TT][NK];
__device__ int   g_count[NE];
__device__ int   g_offset[NE];
__device__ int   g_cursor[NE];
__device__ int   g_slot_token[NSLOT];      // grouped slot -> token
__device__ int   g_slot_of[TT][NK];        // (token,k) -> grouped slot
__device__ float g_aux;

// ---------------- init ----------------------------------------------------
__global__ void init_kernel() {
    int i = threadIdx.x;
    if (i < NE) { g_count[i] = 0; g_cursor[i] = 0; }
    if (i == 0) g_aux = 0.f;
}

// ---------------- router: logits, sigmoid, top-2, aux ---------------------
__global__ void router_kernel(const float* __restrict__ x,
                              const float* __restrict__ rw,
                              const float* __restrict__ rb) {
    int t = blockIdx.x;
    int tid = threadIdx.x;                 // 128 threads
    const float* xr = x + (size_t)t * DDIM;

    float acc[NE];
#pragma unroll
    for (int e = 0; e < NE; e++) acc[e] = 0.f;

    for (int d = tid; d < DDIM; d += 128) {
        float xv = xr[d];
#pragma unroll
        for (int e = 0; e < NE; e++) acc[e] += xv * rw[e * DDIM + d];
    }

    __shared__ float red[NE][128];
#pragma unroll
    for (int e = 0; e < NE; e++) red[e][tid] = acc[e];
    __syncthreads();
    for (int s = 64; s > 0; s >>= 1) {
        if (tid < s) {
#pragma unroll
            for (int e = 0; e < NE; e++) red[e][tid] += red[e][tid + s];
        }
        __syncthreads();
    }

    if (tid == 0) {
        float scores[NE];
        float aux = 0.f;
#pragma unroll
        for (int e = 0; e < NE; e++) {
            float l = red[e][0] + rb[e];
            aux += l * l;
            scores[e] = 1.f / (1.f + expf(-l));
        }
        atomicAdd(&g_aux, aux);

        int i0 = 0;
        for (int e = 1; e < NE; e++) if (scores[e] > scores[i0]) i0 = e;
        int i1 = -1;
        for (int e = 0; e < NE; e++) {
            if (e == i0) continue;
            if (i1 < 0 || scores[e] > scores[i1]) i1 = e;
        }
        float v0 = scores[i0], v1 = scores[i1];
        float inv = 1.f / (v0 + v1 + 1e-6f);
        g_topk_idx[t][0] = i0;  g_topk_idx[t][1] = i1;
        g_topk_w[t][0]   = v0 * inv;  g_topk_w[t][1] = v1 * inv;
        atomicAdd(&g_count[i0], 1);
        atomicAdd(&g_count[i1], 1);
    }
}

// ---------------- group slots by expert (prefix + scatter) ----------------
__global__ void scatter_kernel() {
    int tid = threadIdx.x;                 // 256 threads, single block
    if (tid == 0) {
        int o = 0;
        for (int e = 0; e < NE; e++) { g_offset[e] = o; o += g_count[e]; }
    }
    __syncthreads();
    for (int i = tid; i < NSLOT; i += 256) {
        int t = i >> 1, k = i & 1;
        int e = g_topk_idx[t][k];
        int pos = g_offset[e] + atomicAdd(&g_cursor[e], 1);
        g_slot_token[pos] = t;
        g_slot_of[t][k] = pos;
    }
}

// ---------------- GEMM1: gathered x [n_e, D] @ w12[e] [D, 2H] -------------
// 64x64 tile, TK=16, 256 threads, 4x4 micro-tile per thread
__global__ void gemm1_kernel(const float* __restrict__ x,
                             const float* __restrict__ w12) {
    int e = blockIdx.z;
    int cnt = g_count[e];
    int row0 = blockIdx.y * 64;
    if (row0 >= cnt) return;
    int off = g_offset[e];
    int n0 = blockIdx.x * 64;
    const float* Bp = w12 + (size_t)e * DDIM * H2;

    __shared__ float As[16][64];
    __shared__ float Bs[16][64];
    __shared__ int tok[64];

    int tid = threadIdx.x;
    if (tid < 64) {
        int m = row0 + tid;
        int mm = (m < cnt) ? m : row0;     // clamp out-of-range rows to a valid row
        tok[tid] = g_slot_token[off + mm];
    }
    __syncthreads();

    int ty = tid >> 4, tx = tid & 15;
    int am = tid >> 2, ak = (tid & 3) * 4;
    int bk = tid >> 4, bn = (tid & 15) * 4;
    const float* arow = x + (size_t)tok[am] * DDIM + ak;

    float acc[4][4] = {};
    for (int k0 = 0; k0 < DDIM; k0 += 16) {
        float4 av = *(const float4*)(arow + k0);
        As[ak + 0][am] = av.x; As[ak + 1][am] = av.y;
        As[ak + 2][am] = av.z; As[ak + 3][am] = av.w;
        *(float4*)&Bs[bk][bn] = *(const float4*)(Bp + (size_t)(k0 + bk) * H2 + n0 + bn);
        __syncthreads();
#pragma unroll
        for (int k = 0; k < 16; k++) {
            float4 a = *(float4*)&As[k][ty << 2];
            float4 b = *(float4*)&Bs[k][tx << 2];
            acc[0][0] += a.x * b.x; acc[0][1] += a.x * b.y; acc[0][2] += a.x * b.z; acc[0][3] += a.x * b.w;
            acc[1][0] += a.y * b.x; acc[1][1] += a.y * b.y; acc[1][2] += a.y * b.z; acc[1][3] += a.y * b.w;
            acc[2][0] += a.z * b.x; acc[2][1] += a.z * b.y; acc[2][2] += a.z * b.z; acc[2][3] += a.z * b.w;
            acc[3][0] += a.w * b.x; acc[3][1] += a.w * b.y; acc[3][2] += a.w * b.z; acc[3][3] += a.w * b.w;
        }
        __syncthreads();
    }

    int rows = cnt - row0;
#pragma unroll
    for (int i = 0; i < 4; i++) {
        int m = (ty << 2) + i;
        if (m < rows) {
            float4 v = make_float4(acc[i][0], acc[i][1], acc[i][2], acc[i][3]);
            *(float4*)&g_h12[(size_t)(off + row0 + m) * H2 + n0 + (tx << 2)] = v;
        }
    }
}

// ---------------- SwiGLU: hidden = silu(h1) * h2 --------------------------
__global__ void swiglu_kernel() {
    size_t gid = (size_t)blockIdx.x * blockDim.x + threadIdx.x;
    size_t idx = gid * 4;
    if (idx >= (size_t)NSLOT * HDIM) return;
    size_t r = idx / HDIM, c = idx % HDIM;
    float4 a = *(const float4*)&g_h12[r * H2 + c];
    float4 b = *(const float4*)&g_h12[r * H2 + HDIM + c];
    float4 o;
    o.x = (a.x / (1.f + expf(-a.x))) * b.x;
    o.y = (a.y / (1.f + expf(-a.y))) * b.y;
    o.z = (a.z / (1.f + expf(-a.z))) * b.z;
    o.w = (a.w / (1.f + expf(-a.w))) * b.w;
    *(float4*)&g_hidden[idx] = o;
}

// ---------------- GEMM2: hidden [n_e, H] @ w3[e] [H, D] -------------------
__global__ void gemm2_kernel(const float* __restrict__ w3) {
    int e = blockIdx.z;
    int cnt = g_count[e];
    int row0 = blockIdx.y * 64;
    if (row0 >= cnt) return;
    int off = g_offset[e];
    int n0 = blockIdx.x * 64;
    const float* Bp = w3 + (size_t)e * HDIM * DDIM;

    __shared__ float As[16][64];
    __shared__ float Bs[16][64];

    int tid = threadIdx.x;
    int ty = tid >> 4, tx = tid & 15;
    int am = tid >> 2, ak = (tid & 3) * 4;
    int bk = tid >> 4, bn = (tid & 15) * 4;

    int m = row0 + am;
    if (m >= cnt) m = row0;                // clamp loads; stores are guarded
    const float* arow = g_hidden + (size_t)(off + m) * HDIM + ak;

    float acc[4][4] = {};
    for (int k0 = 0; k0 < HDIM; k0 += 16) {
        float4 av = *(const float4*)(arow + k0);
        As[ak + 0][am] = av.x; As[ak + 1][am] = av.y;
        As[ak + 2][am] = av.z; As[ak + 3][am] = av.w;
        *(float4*)&Bs[bk][bn] = *(const float4*)(Bp + (size_t)(k0 + bk) * DDIM + n0 + bn);
        __syncthreads();
#pragma unroll
        for (int k = 0; k < 16; k++) {
            float4 a = *(float4*)&As[k][ty << 2];
            float4 b = *(float4*)&Bs[k][tx << 2];
            acc[0][0] += a.x * b.x; acc[0][1] += a.x * b.y; acc[0][2] += a.x * b.z; acc[0][3] += a.x * b.w;
            acc[1][0] += a.y * b.x; acc[1][1] += a.y * b.y; acc[1][2] += a.y * b.z; acc[1][3] += a.y * b.w;
            acc[2][0] += a.z * b.x; acc[2][1] += a.z * b.y; acc[2][2] += a.z * b.z; acc[2][3] += a.z * b.w;
            acc[3][0] += a.w * b.x; acc[3][1] += a.w * b.y; acc[3][2] += a.w * b.z; acc[3][3] += a.w * b.w;
        }
        __syncthreads();
    }

    int rows = cnt - row0;
#pragma unroll
    for (int i = 0; i < 4; i++) {
        int mi = (ty << 2) + i;
        if (mi < rows) {
            float4 v = make_float4(acc[i][0], acc[i][1], acc[i][2], acc[i][3]);
            *(float4*)&g_y[(size_t)(off + row0 + mi) * DDIM + n0 + (tx << 2)] = v;
        }
    }
}

// ---------------- combine: out[t] = w0*y[slot0] + w1*y[slot1]; aux --------
__global__ void combine_kernel(float* __restrict__ out, int out_size) {
    size_t gid = (size_t)blockIdx.x * blockDim.x + threadIdx.x;
    size_t idx = gid * 4;
    if (idx < (size_t)TT * DDIM) {
        int t = (int)(idx / DDIM);
        int d = (int)(idx % DDIM);
        int s0 = g_slot_of[t][0], s1 = g_slot_of[t][1];
        float w0 = g_topk_w[t][0], w1 = g_topk_w[t][1];
        float4 y0 = *(const float4*)&g_y[(size_t)s0 * DDIM + d];
        float4 y1 = *(const float4*)&g_y[(size_t)s1 * DDIM + d];
        float4 o;
        o.x = w0 * y0.x + w1 * y1.x;
        o.y = w0 * y0.y + w1 * y1.y;
        o.z = w0 * y0.z + w1 * y1.z;
        o.w = w0 * y0.w + w1 * y1.w;
        *(float4*)&out[idx] = o;
    }
    if (gid == 0 && out_size > TT * DDIM) {
        out[TT * DDIM] = 0.01f * g_aux / (float)(TT * NE);
    }
}

// ---------------- launch ---------------------------------------------------
extern "C" void kernel_launch(void* const* d_in, const int* in_sizes, int n_in,
                              void* d_out, int out_size) {
    const float* x   = (const float*)d_in[0];
    const float* rw  = (const float*)d_in[1];
    const float* rb  = (const float*)d_in[2];
    const float* w12 = (const float*)d_in[3];
    const float* w3  = (const float*)d_in[4];
    float* out = (float*)d_out;

    init_kernel<<<1, 32>>>();
    router_kernel<<<TT, 128>>>(x, rw, rb);
    scatter_kernel<<<1, 256>>>();
    gemm1_kernel<<<dim3(H2 / 64, TT / 64, NE), 256>>>(x, w12);
    swiglu_kernel<<<(NSLOT * HDIM / 4 + 255) / 256, 256>>>();
    gemm2_kernel<<<dim3(DDIM / 64, TT / 64, NE), 256>>>(w3);
    combine_kernel<<<(TT * DDIM / 4 + 255) / 256, 256>>>(out, out_size);
}

// round 3
// speedup vs baseline: 1.8837x; 1.8837x over previous
#include <cuda_runtime.h>
#include <cuda_bf16.h>
#include <math.h>
#include <stdint.h>

// Problem constants
#define TT    2048
#define DDIM  1024
#define HDIM  2048
#define H2    4096
#define NE    8
#define NK    2
#define NSLOT 4096

// GEMM tile config (mma.sync path, compute_103-safe)
#define STAGES 3
#define KC     32                    // bf16 k-elements per chunk (extended K)
#define PITCH  80                    // smem row pitch in bytes (64B data + 16B pad)
#define TILE_BYTES  (128 * PITCH)    // 10240 per operand tile
#define STAGE_BYTES (2 * TILE_BYTES) // A + B
#define GEMM_SMEM   (STAGES * STAGE_BYTES)   // 61440

// ---------------- device scratch ----------------
__device__ __align__(256) float    g_h12[(size_t)NSLOT * H2];      // 64MB
__device__ __align__(256) float    g_y[(size_t)NSLOT * DDIM];      // 16MB
__device__ __align__(256) uint16_t g_xg_hi[(size_t)NSLOT * DDIM];
__device__ __align__(256) uint16_t g_xg_lo[(size_t)NSLOT * DDIM];
__device__ __align__(256) uint16_t g_hid_hi[(size_t)NSLOT * HDIM];
__device__ __align__(256) uint16_t g_hid_lo[(size_t)NSLOT * HDIM];
__device__ __align__(256) uint16_t g_w12t_hi[(size_t)NE * H2 * DDIM];
__device__ __align__(256) uint16_t g_w12t_lo[(size_t)NE * H2 * DDIM];
__device__ __align__(256) uint16_t g_w3t_hi[(size_t)NE * DDIM * HDIM];
__device__ __align__(256) uint16_t g_w3t_lo[(size_t)NE * DDIM * HDIM];
__device__ int   g_topk_idx[TT][NK];
__device__ float g_topk_w[TT][NK];
__device__ int   g_count[NE];
__device__ int   g_offset[NE];
__device__ int   g_cursor[NE];
__device__ int   g_slot_token[NSLOT];
__device__ int   g_slot_of[TT][NK];
__device__ float g_aux;

// ---------------- helpers ----------------
__device__ __forceinline__ uint32_t smem_u32(const void* p) {
    return (uint32_t)__cvta_generic_to_shared(p);
}
__device__ __forceinline__ void bf16_split(float v, uint16_t& hi, uint16_t& lo) {
    __nv_bfloat16 h = __float2bfloat16(v);
    float r = v - __bfloat162float(h);
    __nv_bfloat16 l = __float2bfloat16(r);
    hi = *reinterpret_cast<uint16_t*>(&h);
    lo = *reinterpret_cast<uint16_t*>(&l);
}
__device__ __forceinline__ void cp16(uint32_t dst, const void* src) {
    asm volatile("cp.async.cg.shared.global [%0], [%1], 16;" :: "r"(dst), "l"(src));
}
__device__ __forceinline__ void cp_commit() {
    asm volatile("cp.async.commit_group;" ::: "memory");
}
template<int N>
__device__ __forceinline__ void cp_wait() {
    asm volatile("cp.async.wait_group %0;" :: "n"(N) : "memory");
}
__device__ __forceinline__ void ldsm4(uint32_t* r, uint32_t a) {
    asm volatile("ldmatrix.sync.aligned.m8n8.x4.shared.b16 {%0,%1,%2,%3}, [%4];"
        : "=r"(r[0]), "=r"(r[1]), "=r"(r[2]), "=r"(r[3]) : "r"(a));
}
__device__ __forceinline__ void mma16816(float* c, const uint32_t* a, uint32_t b0, uint32_t b1) {
    asm volatile("mma.sync.aligned.m16n8k16.row.col.f32.bf16.bf16.f32 "
        "{%0,%1,%2,%3},{%4,%5,%6,%7},{%8,%9},{%0,%1,%2,%3};"
        : "+f"(c[0]), "+f"(c[1]), "+f"(c[2]), "+f"(c[3])
        : "r"(a[0]), "r"(a[1]), "r"(a[2]), "r"(a[3]), "r"(b0), "r"(b1));
}

// ---------------- init ----------------
__global__ void init_kernel() {
    int i = threadIdx.x;
    if (i < NE) { g_count[i] = 0; g_cursor[i] = 0; }
    if (i == 0) g_aux = 0.f;
}

// ---------------- router ----------------
__global__ void router_kernel(const float* __restrict__ x,
                              const float* __restrict__ rw,
                              const float* __restrict__ rb) {
    int t = blockIdx.x;
    int tid = threadIdx.x;
    const float* xr = x + (size_t)t * DDIM;

    float acc[NE];
#pragma unroll
    for (int e = 0; e < NE; e++) acc[e] = 0.f;
    for (int d = tid; d < DDIM; d += 128) {
        float xv = xr[d];
#pragma unroll
        for (int e = 0; e < NE; e++) acc[e] += xv * rw[e * DDIM + d];
    }
    __shared__ float red[NE][128];
#pragma unroll
    for (int e = 0; e < NE; e++) red[e][tid] = acc[e];
    __syncthreads();
    for (int s = 64; s > 0; s >>= 1) {
        if (tid < s) {
#pragma unroll
            for (int e = 0; e < NE; e++) red[e][tid] += red[e][tid + s];
        }
        __syncthreads();
    }
    if (tid == 0) {
        float scores[NE];
        float aux = 0.f;
#pragma unroll
        for (int e = 0; e < NE; e++) {
            float l = red[e][0] + rb[e];
            aux += l * l;
            scores[e] = 1.f / (1.f + expf(-l));
        }
        atomicAdd(&g_aux, aux);
        int i0 = 0;
        for (int e = 1; e < NE; e++) if (scores[e] > scores[i0]) i0 = e;
        int i1 = -1;
        for (int e = 0; e < NE; e++) {
            if (e == i0) continue;
            if (i1 < 0 || scores[e] > scores[i1]) i1 = e;
        }
        float v0 = scores[i0], v1 = scores[i1];
        float inv = 1.f / (v0 + v1 + 1e-6f);
        g_topk_idx[t][0] = i0; g_topk_idx[t][1] = i1;
        g_topk_w[t][0] = v0 * inv; g_topk_w[t][1] = v1 * inv;
        atomicAdd(&g_count[i0], 1);
        atomicAdd(&g_count[i1], 1);
    }
}

// ---------------- scatter ----------------
__global__ void scatter_kernel() {
    int tid = threadIdx.x;
    if (tid == 0) {
        int o = 0;
        for (int e = 0; e < NE; e++) { g_offset[e] = o; o += g_count[e]; }
    }
    __syncthreads();
    for (int i = tid; i < NSLOT; i += 256) {
        int t = i >> 1, k = i & 1;
        int e = g_topk_idx[t][k];
        int pos = g_offset[e] + atomicAdd(&g_cursor[e], 1);
        g_slot_token[pos] = t;
        g_slot_of[t][k] = pos;
    }
}

// ---------------- gather + bf16 split of x ----------------
__global__ void gather_split_kernel(const float* __restrict__ x) {
    int idx = blockIdx.x * 256 + threadIdx.x;
    int s = idx >> 7;
    int c = (idx & 127) * 8;
    int t = g_slot_token[s];
    const float* xr = x + (size_t)t * DDIM + c;
    float4 a = *(const float4*)xr;
    float4 b = *(const float4*)(xr + 4);
    float v[8] = {a.x, a.y, a.z, a.w, b.x, b.y, b.z, b.w};
    uint16_t h[8], l[8];
#pragma unroll
    for (int i = 0; i < 8; i++) bf16_split(v[i], h[i], l[i]);
    uint4 hv = make_uint4((uint32_t)h[0] | ((uint32_t)h[1] << 16),
                          (uint32_t)h[2] | ((uint32_t)h[3] << 16),
                          (uint32_t)h[4] | ((uint32_t)h[5] << 16),
                          (uint32_t)h[6] | ((uint32_t)h[7] << 16));
    uint4 lv = make_uint4((uint32_t)l[0] | ((uint32_t)l[1] << 16),
                          (uint32_t)l[2] | ((uint32_t)l[3] << 16),
                          (uint32_t)l[4] | ((uint32_t)l[5] << 16),
                          (uint32_t)l[6] | ((uint32_t)l[7] << 16));
    *(uint4*)&g_xg_hi[(size_t)s * DDIM + c] = hv;
    *(uint4*)&g_xg_lo[(size_t)s * DDIM + c] = lv;
}

// ---------------- transpose + bf16 split of weights ----------------
template<int MODE>
__global__ void transpose_split_kernel(const float* __restrict__ in) {
    constexpr int Kd = (MODE == 0) ? DDIM : HDIM;
    constexpr int Nd = (MODE == 0) ? H2 : DDIM;
    uint16_t* ohi = (MODE == 0) ? g_w12t_hi : g_w3t_hi;
    uint16_t* olo = (MODE == 0) ? g_w12t_lo : g_w3t_lo;

    __shared__ float tbuf[32][33];
    int e = blockIdx.z;
    const float* src = in + (size_t)e * Kd * Nd;
    uint16_t* dhi = ohi + (size_t)e * Kd * Nd;
    uint16_t* dlo = olo + (size_t)e * Kd * Nd;

    int n = blockIdx.x * 32 + threadIdx.x;
    int k0 = blockIdx.y * 32;
#pragma unroll
    for (int j = 0; j < 32; j += 8)
        tbuf[threadIdx.y + j][threadIdx.x] = src[(size_t)(k0 + threadIdx.y + j) * Nd + n];
    __syncthreads();
    int k = k0 + threadIdx.x;
    int nb = blockIdx.x * 32;
#pragma unroll
    for (int j = 0; j < 32; j += 8) {
        float v = tbuf[threadIdx.x][threadIdx.y + j];
        uint16_t h, l;
        bf16_split(v, h, l);
        size_t o = (size_t)(nb + threadIdx.y + j) * Kd + k;
        dhi[o] = h; dlo[o] = l;
    }
}

// ---------------- grouped GEMM via mma.sync (split-bf16, extended K) ------
// MODE 0: A = g_xg (hi/lo) [slot,DDIM], B = g_w12t, C = g_h12 [slot,H2]
// MODE 1: A = g_hid (hi/lo) [slot,HDIM], B = g_w3t,  C = g_y  [slot,DDIM]
template<int MODE>
__global__ void __launch_bounds__(256) moe_gemm_mma() {
    constexpr int KDIM = (MODE == 0) ? DDIM : HDIM;
    constexpr int NTOT = (MODE == 0) ? H2 : DDIM;
    constexpr int NC = 3 * KDIM / KC;     // extended-K chunks
    const uint16_t* Ahi = (MODE == 0) ? g_xg_hi : g_hid_hi;
    const uint16_t* Alo = (MODE == 0) ? g_xg_lo : g_hid_lo;
    float* Out = (MODE == 0) ? g_h12 : g_y;

    const int e = blockIdx.z;
    const int cnt = g_count[e];
    const int row0 = blockIdx.y * 128;
    if (row0 >= cnt) return;
    const int off = g_offset[e];
    const int n0 = blockIdx.x * 128;
    const uint16_t* Bhi = ((MODE == 0) ? g_w12t_hi : g_w3t_hi) + (size_t)e * NTOT * KDIM;
    const uint16_t* Blo = ((MODE == 0) ? g_w12t_lo : g_w3t_lo) + (size_t)e * NTOT * KDIM;

    extern __shared__ __align__(128) char smem[];
    const uint32_t sb = smem_u32(smem);
    const int tid = threadIdx.x;
    const int lane = tid & 31;
    const int wid = tid >> 5;
    const int wm = (wid & 1) * 64;        // warp m-offset within tile
    const int wn = (wid >> 1) * 32;       // warp n-offset within tile

    // per-thread load tasks: A tasks t, t+256; B tasks t, t+256 (512 each)
    const int ar0 = tid >> 2, ar1 = (tid + 256) >> 2;
    const int as0 = tid & 3,  as1 = (tid + 256) & 3;
    int gra0 = row0 + ar0; if (gra0 >= cnt) gra0 = row0;
    int gra1 = row0 + ar1; if (gra1 >= cnt) gra1 = row0;
    const size_t aoff0 = (size_t)(off + gra0) * KDIM + as0 * 8;
    const size_t aoff1 = (size_t)(off + gra1) * KDIM + as1 * 8;
    const size_t boff0 = (size_t)(n0 + ar0) * KDIM + as0 * 8;
    const size_t boff1 = (size_t)(n0 + ar1) * KDIM + as1 * 8;
    const uint32_t da0 = ar0 * PITCH + as0 * 16;
    const uint32_t da1 = ar1 * PITCH + as1 * 16;

    auto issue = [&](int c) {
        int term = c % 3;
        int k0 = (c / 3) * KC;
        const uint16_t* As = (term == 2) ? Alo : Ahi;
        const uint16_t* Bs = (term == 1) ? Blo : Bhi;
        uint32_t st = sb + (c % STAGES) * STAGE_BYTES;
        cp16(st + da0, As + aoff0 + k0);
        cp16(st + da1, As + aoff1 + k0);
        cp16(st + TILE_BYTES + da0, Bs + boff0 + k0);
        cp16(st + TILE_BYTES + da1, Bs + boff1 + k0);
        cp_commit();
    };

    float acc[4][4][4];
#pragma unroll
    for (int i = 0; i < 4; i++)
#pragma unroll
        for (int j = 0; j < 4; j++)
#pragma unroll
            for (int q = 0; q < 4; q++) acc[i][j][q] = 0.f;

    // prologue
#pragma unroll
    for (int c = 0; c < STAGES - 1; c++) issue(c);

    const uint32_t lmoff = (lane & 15) * PITCH + (lane >> 4) * 16;

    for (int c = 0; c < NC; ++c) {
        cp_wait<STAGES - 2>();
        __syncthreads();
        if (c + STAGES - 1 < NC) issue(c + STAGES - 1);

        uint32_t Ab = sb + (c % STAGES) * STAGE_BYTES;
        uint32_t Bb = Ab + TILE_BYTES;
#pragma unroll
        for (int kh = 0; kh < 2; kh++) {
            uint32_t a[4][4];
#pragma unroll
            for (int i = 0; i < 4; i++)
                ldsm4(a[i], Ab + lmoff + (uint32_t)(wm + i * 16) * PITCH + kh * 32);
            uint32_t bq[2][4];
#pragma unroll
            for (int h = 0; h < 2; h++)
                ldsm4(bq[h], Bb + lmoff + (uint32_t)(wn + h * 16) * PITCH + kh * 32);
#pragma unroll
            for (int i = 0; i < 4; i++)
#pragma unroll
                for (int j = 0; j < 4; j++)
                    mma16816(acc[i][j], a[i], bq[j >> 1][j & 1], bq[j >> 1][(j & 1) + 2]);
        }
        __syncthreads();
    }

    // epilogue: direct stores, guarded by valid rows
    const int rows_valid = cnt - row0;
#pragma unroll
    for (int i = 0; i < 4; i++) {
        int r_lo = wm + i * 16 + (lane >> 2);
        int r_hi = r_lo + 8;
#pragma unroll
        for (int j = 0; j < 4; j++) {
            int col = n0 + wn + j * 8 + (lane & 3) * 2;
            if (r_lo < rows_valid) {
                float2 v = make_float2(acc[i][j][0], acc[i][j][1]);
                *(float2*)&Out[(size_t)(off + row0 + r_lo) * NTOT + col] = v;
            }
            if (r_hi < rows_valid) {
                float2 v = make_float2(acc[i][j][2], acc[i][j][3]);
                *(float2*)&Out[(size_t)(off + row0 + r_hi) * NTOT + col] = v;
            }
        }
    }
}

// ---------------- SwiGLU + bf16 split ----------------
__global__ void swiglu_split_kernel() {
    int idx = blockIdx.x * 256 + threadIdx.x;
    int s = idx >> 8;
    int c = (idx & 255) * 8;
    const float* p1 = g_h12 + (size_t)s * H2 + c;
    const float* p2 = p1 + HDIM;
    float4 a0 = *(const float4*)p1;
    float4 a1 = *(const float4*)(p1 + 4);
    float4 b0 = *(const float4*)p2;
    float4 b1 = *(const float4*)(p2 + 4);
    float va[8] = {a0.x, a0.y, a0.z, a0.w, a1.x, a1.y, a1.z, a1.w};
    float vb[8] = {b0.x, b0.y, b0.z, b0.w, b1.x, b1.y, b1.z, b1.w};
    uint16_t h[8], l[8];
#pragma unroll
    for (int i = 0; i < 8; i++) {
        float o = (va[i] / (1.f + expf(-va[i]))) * vb[i];
        bf16_split(o, h[i], l[i]);
    }
    uint4 hv = make_uint4((uint32_t)h[0] | ((uint32_t)h[1] << 16),
                          (uint32_t)h[2] | ((uint32_t)h[3] << 16),
                          (uint32_t)h[4] | ((uint32_t)h[5] << 16),
                          (uint32_t)h[6] | ((uint32_t)h[7] << 16));
    uint4 lv = make_uint4((uint32_t)l[0] | ((uint32_t)l[1] << 16),
                          (uint32_t)l[2] | ((uint32_t)l[3] << 16),
                          (uint32_t)l[4] | ((uint32_t)l[5] << 16),
                          (uint32_t)l[6] | ((uint32_t)l[7] << 16));
    *(uint4*)&g_hid_hi[(size_t)s * HDIM + c] = hv;
    *(uint4*)&g_hid_lo[(size_t)s * HDIM + c] = lv;
}

// ---------------- combine ----------------
__global__ void combine_kernel(float* __restrict__ out, int out_size) {
    size_t gid = (size_t)blockIdx.x * blockDim.x + threadIdx.x;
    size_t idx = gid * 4;
    if (idx < (size_t)TT * DDIM) {
        int t = (int)(idx / DDIM);
        int d = (int)(idx % DDIM);
        int s0 = g_slot_of[t][0], s1 = g_slot_of[t][1];
        float w0 = g_topk_w[t][0], w1 = g_topk_w[t][1];
        float4 y0 = *(const float4*)&g_y[(size_t)s0 * DDIM + d];
        float4 y1 = *(const float4*)&g_y[(size_t)s1 * DDIM + d];
        float4 o;
        o.x = w0 * y0.x + w1 * y1.x;
        o.y = w0 * y0.y + w1 * y1.y;
        o.z = w0 * y0.z + w1 * y1.z;
        o.w = w0 * y0.w + w1 * y1.w;
        *(float4*)&out[idx] = o;
    }
    if (gid == 0 && out_size > TT * DDIM) {
        out[TT * DDIM] = 0.01f * g_aux / (float)(TT * NE);
    }
}

// ---------------- launch ----------------
extern "C" void kernel_launch(void* const* d_in, const int* in_sizes, int n_in,
                              void* d_out, int out_size) {
    const float* x   = (const float*)d_in[0];
    const float* rw  = (const float*)d_in[1];
    const float* rb  = (const float*)d_in[2];
    const float* w12 = (const float*)d_in[3];
    const float* w3  = (const float*)d_in[4];
    float* out = (float*)d_out;

    cudaFuncSetAttribute(moe_gemm_mma<0>, cudaFuncAttributeMaxDynamicSharedMemorySize, GEMM_SMEM);
    cudaFuncSetAttribute(moe_gemm_mma<1>, cudaFuncAttributeMaxDynamicSharedMemorySize, GEMM_SMEM);

    init_kernel<<<1, 32>>>();
    router_kernel<<<TT, 128>>>(x, rw, rb);
    scatter_kernel<<<1, 256>>>();
    gather_split_kernel<<<(NSLOT * DDIM / 8) / 256, 256>>>(x);
    transpose_split_kernel<0><<<dim3(H2 / 32, DDIM / 32, NE), dim3(32, 8)>>>(w12);
    transpose_split_kernel<1><<<dim3(DDIM / 32, HDIM / 32, NE), dim3(32, 8)>>>(w3);
    moe_gemm_mma<0><<<dim3(H2 / 128, NSLOT / 128, NE), 256, GEMM_SMEM>>>();
    swiglu_split_kernel<<<(NSLOT * HDIM / 8) / 256, 256>>>();
    moe_gemm_mma<1><<<dim3(DDIM / 128, NSLOT / 128, NE), 256, GEMM_SMEM>>>();
    combine_kernel<<<(TT * DDIM / 4) / 256, 256>>>(out, out_size);
}

// round 4
// speedup vs baseline: 2.4395x; 1.2950x over previous
#include <cuda_runtime.h>
#include <cuda_bf16.h>
#include <math.h>
#include <stdint.h>

// Problem constants
#define TT    2048
#define DDIM  1024
#define HDIM  2048
#define H2    4096
#define NE    8
#define NK    2
#define NSLOT 4096

// GEMM tile config
#define KC     64                     // k elements per chunk (=128B row)
#define TILE_B 16384                  // 128 rows * 128B
#define OFF_AHI 0
#define OFF_ALO 16384
#define OFF_BHI 32768
#define OFF_BLO 49152
#define STAGE_BYTES 65536
#define GEMM_SMEM   (3 * STAGE_BYTES) // 196608

// ---------------- device scratch ----------------
__device__ __align__(256) float    g_y[(size_t)NSLOT * DDIM];
__device__ __align__(256) uint16_t g_xg_hi[(size_t)NSLOT * DDIM];
__device__ __align__(256) uint16_t g_xg_lo[(size_t)NSLOT * DDIM];
__device__ __align__(256) uint16_t g_hid_hi[(size_t)NSLOT * HDIM];
__device__ __align__(256) uint16_t g_hid_lo[(size_t)NSLOT * HDIM];
__device__ __align__(256) uint16_t g_w12t_hi[(size_t)NE * H2 * DDIM];
__device__ __align__(256) uint16_t g_w12t_lo[(size_t)NE * H2 * DDIM];
__device__ __align__(256) uint16_t g_w3t_hi[(size_t)NE * DDIM * HDIM];
__device__ __align__(256) uint16_t g_w3t_lo[(size_t)NE * DDIM * HDIM];
__device__ int   g_topk_idx[TT][NK];
__device__ float g_topk_w[TT][NK];
__device__ int   g_count[NE];
__device__ int   g_offset[NE];
__device__ int   g_cursor[NE];
__device__ int   g_slot_token[NSLOT];
__device__ int   g_slot_of[TT][NK];
__device__ float g_aux;

// ---------------- helpers ----------------
__device__ __forceinline__ uint32_t smem_u32(const void* p) {
    return (uint32_t)__cvta_generic_to_shared(p);
}
__device__ __forceinline__ void bf16_split(float v, uint16_t& hi, uint16_t& lo) {
    __nv_bfloat16 h = __float2bfloat16(v);
    float r = v - __bfloat162float(h);
    __nv_bfloat16 l = __float2bfloat16(r);
    hi = *reinterpret_cast<uint16_t*>(&h);
    lo = *reinterpret_cast<uint16_t*>(&l);
}
__device__ __forceinline__ void cp16(uint32_t dst, const void* src) {
    asm volatile("cp.async.cg.shared.global [%0], [%1], 16;" :: "r"(dst), "l"(src));
}
__device__ __forceinline__ void cp_commit() {
    asm volatile("cp.async.commit_group;" ::: "memory");
}
template<int N>
__device__ __forceinline__ void cp_wait() {
    asm volatile("cp.async.wait_group %0;" :: "n"(N) : "memory");
}
__device__ __forceinline__ void ldsm4(uint32_t* r, uint32_t a) {
    asm volatile("ldmatrix.sync.aligned.m8n8.x4.shared.b16 {%0,%1,%2,%3}, [%4];"
        : "=r"(r[0]), "=r"(r[1]), "=r"(r[2]), "=r"(r[3]) : "r"(a));
}
__device__ __forceinline__ void mma16816(float* c, const uint32_t* a, uint32_t b0, uint32_t b1) {
    asm volatile("mma.sync.aligned.m16n8k16.row.col.f32.bf16.bf16.f32 "
        "{%0,%1,%2,%3},{%4,%5,%6,%7},{%8,%9},{%0,%1,%2,%3};"
        : "+f"(c[0]), "+f"(c[1]), "+f"(c[2]), "+f"(c[3])
        : "r"(a[0]), "r"(a[1]), "r"(a[2]), "r"(a[3]), "r"(b0), "r"(b1));
}

// ---------------- init ----------------
__global__ void init_kernel() {
    int i = threadIdx.x;
    if (i < NE) { g_count[i] = 0; g_cursor[i] = 0; }
    if (i == 0) g_aux = 0.f;
}

// ---------------- router ----------------
__global__ void router_kernel(const float* __restrict__ x,
                              const float* __restrict__ rw,
                              const float* __restrict__ rb) {
    int t = blockIdx.x;
    int tid = threadIdx.x;
    const float* xr = x + (size_t)t * DDIM;

    float acc[NE];
#pragma unroll
    for (int e = 0; e < NE; e++) acc[e] = 0.f;
    for (int d = tid; d < DDIM; d += 128) {
        float xv = xr[d];
#pragma unroll
        for (int e = 0; e < NE; e++) acc[e] += xv * rw[e * DDIM + d];
    }
    __shared__ float red[NE][128];
#pragma unroll
    for (int e = 0; e < NE; e++) red[e][tid] = acc[e];
    __syncthreads();
    for (int s = 64; s > 0; s >>= 1) {
        if (tid < s) {
#pragma unroll
            for (int e = 0; e < NE; e++) red[e][tid] += red[e][tid + s];
        }
        __syncthreads();
    }
    if (tid == 0) {
        float scores[NE];
        float aux = 0.f;
#pragma unroll
        for (int e = 0; e < NE; e++) {
            float l = red[e][0] + rb[e];
            aux += l * l;
            scores[e] = 1.f / (1.f + expf(-l));
        }
        atomicAdd(&g_aux, aux);
        int i0 = 0;
        for (int e = 1; e < NE; e++) if (scores[e] > scores[i0]) i0 = e;
        int i1 = -1;
        for (int e = 0; e < NE; e++) {
            if (e == i0) continue;
            if (i1 < 0 || scores[e] > scores[i1]) i1 = e;
        }
        float v0 = scores[i0], v1 = scores[i1];
        float inv = 1.f / (v0 + v1 + 1e-6f);
        g_topk_idx[t][0] = i0; g_topk_idx[t][1] = i1;
        g_topk_w[t][0] = v0 * inv; g_topk_w[t][1] = v1 * inv;
        atomicAdd(&g_count[i0], 1);
        atomicAdd(&g_count[i1], 1);
    }
}

// ---------------- scatter ----------------
__global__ void scatter_kernel() {
    int tid = threadIdx.x;
    if (tid == 0) {
        int o = 0;
        for (int e = 0; e < NE; e++) { g_offset[e] = o; o += g_count[e]; }
    }
    __syncthreads();
    for (int i = tid; i < NSLOT; i += 256) {
        int t = i >> 1, k = i & 1;
        int e = g_topk_idx[t][k];
        int pos = g_offset[e] + atomicAdd(&g_cursor[e], 1);
        g_slot_token[pos] = t;
        g_slot_of[t][k] = pos;
    }
}

// ---------------- gather + bf16 split of x ----------------
__global__ void gather_split_kernel(const float* __restrict__ x) {
    int idx = blockIdx.x * 256 + threadIdx.x;
    int s = idx >> 7;
    int c = (idx & 127) * 8;
    int t = g_slot_token[s];
    const float* xr = x + (size_t)t * DDIM + c;
    float4 a = *(const float4*)xr;
    float4 b = *(const float4*)(xr + 4);
    float v[8] = {a.x, a.y, a.z, a.w, b.x, b.y, b.z, b.w};
    uint16_t h[8], l[8];
#pragma unroll
    for (int i = 0; i < 8; i++) bf16_split(v[i], h[i], l[i]);
    uint4 hv = make_uint4((uint32_t)h[0] | ((uint32_t)h[1] << 16),
                          (uint32_t)h[2] | ((uint32_t)h[3] << 16),
                          (uint32_t)h[4] | ((uint32_t)h[5] << 16),
                          (uint32_t)h[6] | ((uint32_t)h[7] << 16));
    uint4 lv = make_uint4((uint32_t)l[0] | ((uint32_t)l[1] << 16),
                          (uint32_t)l[2] | ((uint32_t)l[3] << 16),
                          (uint32_t)l[4] | ((uint32_t)l[5] << 16),
                          (uint32_t)l[6] | ((uint32_t)l[7] << 16));
    *(uint4*)&g_xg_hi[(size_t)s * DDIM + c] = hv;
    *(uint4*)&g_xg_lo[(size_t)s * DDIM + c] = lv;
}

// ---------------- transpose + bf16 split of weights ----------------
template<int MODE>
__global__ void transpose_split_kernel(const float* __restrict__ in) {
    constexpr int Kd = (MODE == 0) ? DDIM : HDIM;
    constexpr int Nd = (MODE == 0) ? H2 : DDIM;
    uint16_t* ohi = (MODE == 0) ? g_w12t_hi : g_w3t_hi;
    uint16_t* olo = (MODE == 0) ? g_w12t_lo : g_w3t_lo;

    __shared__ float tbuf[32][33];
    int e = blockIdx.z;
    const float* src = in + (size_t)e * Kd * Nd;
    uint16_t* dhi = ohi + (size_t)e * Kd * Nd;
    uint16_t* dlo = olo + (size_t)e * Kd * Nd;

    int n = blockIdx.x * 32 + threadIdx.x;
    int k0 = blockIdx.y * 32;
#pragma unroll
    for (int j = 0; j < 32; j += 8)
        tbuf[threadIdx.y + j][threadIdx.x] = src[(size_t)(k0 + threadIdx.y + j) * Nd + n];
    __syncthreads();
    int k = k0 + threadIdx.x;
    int nb = blockIdx.x * 32;
#pragma unroll
    for (int j = 0; j < 32; j += 8) {
        float v = tbuf[threadIdx.x][threadIdx.y + j];
        uint16_t h, l;
        bf16_split(v, h, l);
        size_t o = (size_t)(nb + threadIdx.y + j) * Kd + k;
        dhi[o] = h; dlo[o] = l;
    }
}

// ---------------- grouped GEMM via mma.sync, split-bf16 3-term, KC=64 -----
// MODE 0: A = g_xg [slot,DDIM], B = g_w12t (paired h1/h2 cols), epilogue = SwiGLU
//         writes g_hid hi/lo [slot, HDIM]  (grid.x = HDIM/64)
// MODE 1: A = g_hid [slot,HDIM], B = g_w3t, C = g_y [slot,DDIM] (grid.x = DDIM/128)
template<int MODE>
__global__ void __launch_bounds__(256) moe_gemm_mma() {
    constexpr int KDIM = (MODE == 0) ? DDIM : HDIM;
    constexpr int NTOT = (MODE == 0) ? H2 : DDIM;
    constexpr int NC = KDIM / KC;
    const uint16_t* Ahi = (MODE == 0) ? g_xg_hi : g_hid_hi;
    const uint16_t* Alo = (MODE == 0) ? g_xg_lo : g_hid_lo;

    const int e = blockIdx.z;
    const int cnt = g_count[e];
    const int row0 = blockIdx.y * 128;
    if (row0 >= cnt) return;
    const int off = g_offset[e];
    const int n0 = (MODE == 0) ? blockIdx.x * 64 : blockIdx.x * 128;
    const uint16_t* Bhi = ((MODE == 0) ? g_w12t_hi : g_w3t_hi) + (size_t)e * NTOT * KDIM;
    const uint16_t* Blo = ((MODE == 0) ? g_w12t_lo : g_w3t_lo) + (size_t)e * NTOT * KDIM;

    extern __shared__ __align__(128) char smem[];
    const uint32_t sb = smem_u32(smem);
    const int tid = threadIdx.x;
    const int lane = tid & 31;
    const int wid = tid >> 5;
    const int wm = (wid & 1) * 64;
    const int wn = (wid >> 1) * 32;

    // --- per-thread cp.async tasks: 4 (row,chunk) units per tile ---
    uint32_t dsto[4];
    size_t   asrc[4], bsrc[4];
#pragma unroll
    for (int q = 0; q < 4; q++) {
        int u = tid + q * 256;
        int r = u >> 3, cs = u & 7;
        dsto[q] = (uint32_t)(r * 128 + ((cs ^ (r & 7)) << 4));
        int ar = row0 + r; if (ar >= cnt) ar = cnt - 1;
        asrc[q] = (size_t)(off + ar) * KDIM + cs * 8;
        int ne;
        if (MODE == 0) ne = (r < 64) ? (n0 + r) : (HDIM + n0 + r - 64);
        else           ne = n0 + r;
        bsrc[q] = (size_t)ne * KDIM + cs * 8;
    }

    auto issue = [&](int c) {
        uint32_t st = sb + (c % 3) * STAGE_BYTES;
        int k0 = c * KC;
#pragma unroll
        for (int q = 0; q < 4; q++) {
            cp16(st + OFF_AHI + dsto[q], Ahi + asrc[q] + k0);
            cp16(st + OFF_ALO + dsto[q], Alo + asrc[q] + k0);
            cp16(st + OFF_BHI + dsto[q], Bhi + bsrc[q] + k0);
            cp16(st + OFF_BLO + dsto[q], Blo + bsrc[q] + k0);
        }
        cp_commit();
    };

    float acc[4][4][4];
#pragma unroll
    for (int i = 0; i < 4; i++)
#pragma unroll
        for (int j = 0; j < 4; j++)
#pragma unroll
            for (int q = 0; q < 4; q++) acc[i][j][q] = 0.f;

    // ldmatrix row precompute
    const int lane15 = lane & 15, laneh = lane >> 4;
    uint32_t rA128[4], rB128[2];
    int rA7[4], rB7[2];
#pragma unroll
    for (int i = 0; i < 4; i++) {
        int r = wm + i * 16 + lane15;
        rA128[i] = r * 128; rA7[i] = r & 7;
    }
#pragma unroll
    for (int h = 0; h < 2; h++) {
        int r = wn + h * 16 + lane15;
        rB128[h] = r * 128; rB7[h] = r & 7;
    }

    issue(0);
    if (NC > 1) issue(1);

    for (int c = 0; c < NC; ++c) {
        if (c + 2 < NC) { cp_wait<1>(); } else { cp_wait<0>(); }
        __syncthreads();
        if (c + 2 < NC) issue(c + 2);

        uint32_t S = sb + (c % 3) * STAGE_BYTES;
#pragma unroll
        for (int kh = 0; kh < 4; kh++) {
            int cc = kh * 2 + laneh;
            uint32_t ah[4][4], al[4][4], bh[2][4], bl[2][4];
#pragma unroll
            for (int i = 0; i < 4; i++) {
                uint32_t o = rA128[i] + (uint32_t)((cc ^ rA7[i]) << 4);
                ldsm4(ah[i], S + OFF_AHI + o);
                ldsm4(al[i], S + OFF_ALO + o);
            }
#pragma unroll
            for (int h = 0; h < 2; h++) {
                uint32_t o = rB128[h] + (uint32_t)((cc ^ rB7[h]) << 4);
                ldsm4(bh[h], S + OFF_BHI + o);
                ldsm4(bl[h], S + OFF_BLO + o);
            }
#pragma unroll
            for (int i = 0; i < 4; i++)
#pragma unroll
                for (int j = 0; j < 4; j++) {
                    const uint32_t* bhj = bh[j >> 1];
                    const uint32_t* blj = bl[j >> 1];
                    int s0 = j & 1, s1 = (j & 1) + 2;
                    mma16816(acc[i][j], ah[i], bhj[s0], bhj[s1]);   // hi*hi
                    mma16816(acc[i][j], ah[i], blj[s0], blj[s1]);   // hi*lo
                    mma16816(acc[i][j], al[i], bhj[s0], bhj[s1]);   // lo*hi
                }
        }
        __syncthreads();
    }

    const int rows_valid = (cnt - row0 < 128) ? (cnt - row0) : 128;

    if (MODE == 0) {
        // stage acc to smem, fuse SwiGLU: cols 0-63 = h1, 64-127 = h2
        float* ebuf = (float*)smem;   // pitch 132 floats
#pragma unroll
        for (int i = 0; i < 4; i++) {
            int r_lo = wm + i * 16 + (lane >> 2);
            int r_hi = r_lo + 8;
#pragma unroll
            for (int j = 0; j < 4; j++) {
                int col = wn + j * 8 + (lane & 3) * 2;
                *(float2*)&ebuf[r_lo * 132 + col] = make_float2(acc[i][j][0], acc[i][j][1]);
                *(float2*)&ebuf[r_hi * 132 + col] = make_float2(acc[i][j][2], acc[i][j][3]);
            }
        }
        __syncthreads();
#pragma unroll
        for (int it = 0; it < 16; it++) {
            int idx = tid + it * 256;           // 4096 col-pairs
            int row = idx >> 5;
            int cp = (idx & 31) * 2;
            if (row < rows_valid) {
                float h1a = ebuf[row * 132 + cp];
                float h1b = ebuf[row * 132 + cp + 1];
                float h2a = ebuf[row * 132 + 64 + cp];
                float h2b = ebuf[row * 132 + 64 + cp + 1];
                float oa = (h1a / (1.f + expf(-h1a))) * h2a;
                float ob = (h1b / (1.f + expf(-h1b))) * h2b;
                uint16_t ha, la, hb, lb;
                bf16_split(oa, ha, la);
                bf16_split(ob, hb, lb);
                size_t go = (size_t)(off + row0 + row) * HDIM + n0 + cp;
                *(uint32_t*)&g_hid_hi[go] = (uint32_t)ha | ((uint32_t)hb << 16);
                *(uint32_t*)&g_hid_lo[go] = (uint32_t)la | ((uint32_t)lb << 16);
            }
        }
    } else {
        float* Out = g_y;
#pragma unroll
        for (int i = 0; i < 4; i++) {
            int r_lo = wm + i * 16 + (lane >> 2);
            int r_hi = r_lo + 8;
#pragma unroll
            for (int j = 0; j < 4; j++) {
                int col = n0 + wn + j * 8 + (lane & 3) * 2;
                if (r_lo < rows_valid)
                    *(float2*)&Out[(size_t)(off + row0 + r_lo) * NTOT + col] =
                        make_float2(acc[i][j][0], acc[i][j][1]);
                if (r_hi < rows_valid)
                    *(float2*)&Out[(size_t)(off + row0 + r_hi) * NTOT + col] =
                        make_float2(acc[i][j][2], acc[i][j][3]);
            }
        }
    }
}

// ---------------- combine ----------------
__global__ void combine_kernel(float* __restrict__ out, int out_size) {
    size_t gid = (size_t)blockIdx.x * blockDim.x + threadIdx.x;
    size_t idx = gid * 4;
    if (idx < (size_t)TT * DDIM) {
        int t = (int)(idx / DDIM);
        int d = (int)(idx % DDIM);
        int s0 = g_slot_of[t][0], s1 = g_slot_of[t][1];
        float w0 = g_topk_w[t][0], w1 = g_topk_w[t][1];
        float4 y0 = *(const float4*)&g_y[(size_t)s0 * DDIM + d];
        float4 y1 = *(const float4*)&g_y[(size_t)s1 * DDIM + d];
        float4 o;
        o.x = w0 * y0.x + w1 * y1.x;
        o.y = w0 * y0.y + w1 * y1.y;
        o.z = w0 * y0.z + w1 * y1.z;
        o.w = w0 * y0.w + w1 * y1.w;
        *(float4*)&out[idx] = o;
    }
    if (gid == 0 && out_size > TT * DDIM) {
        out[TT * DDIM] = 0.01f * g_aux / (float)(TT * NE);
    }
}

// ---------------- launch ----------------
extern "C" void kernel_launch(void* const* d_in, const int* in_sizes, int n_in,
                              void* d_out, int out_size) {
    const float* x   = (const float*)d_in[0];
    const float* rw  = (const float*)d_in[1];
    const float* rb  = (const float*)d_in[2];
    const float* w12 = (const float*)d_in[3];
    const float* w3  = (const float*)d_in[4];
    float* out = (float*)d_out;

    cudaFuncSetAttribute(moe_gemm_mma<0>, cudaFuncAttributeMaxDynamicSharedMemorySize, GEMM_SMEM);
    cudaFuncSetAttribute(moe_gemm_mma<1>, cudaFuncAttributeMaxDynamicSharedMemorySize, GEMM_SMEM);

    init_kernel<<<1, 32>>>();
    router_kernel<<<TT, 128>>>(x, rw, rb);
    scatter_kernel<<<1, 256>>>();
    gather_split_kernel<<<(NSLOT * DDIM / 8) / 256, 256>>>(x);
    transpose_split_kernel<0><<<dim3(H2 / 32, DDIM / 32, NE), dim3(32, 8)>>>(w12);
    transpose_split_kernel<1><<<dim3(DDIM / 32, HDIM / 32, NE), dim3(32, 8)>>>(w3);
    moe_gemm_mma<0><<<dim3(HDIM / 64, NSLOT / 128, NE), 256, GEMM_SMEM>>>();
    moe_gemm_mma<1><<<dim3(DDIM / 128, NSLOT / 128, NE), 256, GEMM_SMEM>>>();
    combine_kernel<<<(TT * DDIM / 4) / 256, 256>>>(out, out_size);
}

// round 5
// speedup vs baseline: 2.5343x; 1.0389x over previous
#include <cuda_runtime.h>
#include <cuda_bf16.h>
#include <math.h>
#include <stdint.h>

// Problem constants
#define TT    2048
#define DDIM  1024
#define HDIM  2048
#define H2    4096
#define NE    8
#define NK    2
#define NSLOT 4096

// GEMM tile config
#define KC     64                     // k elements per chunk (=128B row)
#define OFF_AHI 0
#define OFF_ALO 16384
#define OFF_BHI 32768
#define OFF_BLO 49152
#define STAGE_BYTES 65536
#define GEMM_SMEM   (3 * STAGE_BYTES) // 196608
#define GTHREADS 512

// ---------------- device scratch ----------------
__device__ __align__(256) float    g_y[(size_t)NSLOT * DDIM];
__device__ __align__(256) uint16_t g_xg_hi[(size_t)NSLOT * DDIM];
__device__ __align__(256) uint16_t g_xg_lo[(size_t)NSLOT * DDIM];
__device__ __align__(256) uint16_t g_hid_hi[(size_t)NSLOT * HDIM];
__device__ __align__(256) uint16_t g_hid_lo[(size_t)NSLOT * HDIM];
__device__ __align__(256) uint16_t g_w12t_hi[(size_t)NE * H2 * DDIM];
__device__ __align__(256) uint16_t g_w12t_lo[(size_t)NE * H2 * DDIM];
__device__ __align__(256) uint16_t g_w3t_hi[(size_t)NE * DDIM * HDIM];
__device__ __align__(256) uint16_t g_w3t_lo[(size_t)NE * DDIM * HDIM];
__device__ int   g_topk_idx[TT][NK];
__device__ float g_topk_w[TT][NK];
__device__ int   g_count[NE];
__device__ int   g_offset[NE];
__device__ int   g_cursor[NE];
__device__ int   g_slot_token[NSLOT];
__device__ int   g_slot_of[TT][NK];
__device__ float g_aux;

// ---------------- helpers ----------------
__device__ __forceinline__ uint32_t smem_u32(const void* p) {
    return (uint32_t)__cvta_generic_to_shared(p);
}
__device__ __forceinline__ void bf16_split(float v, uint16_t& hi, uint16_t& lo) {
    __nv_bfloat16 h = __float2bfloat16(v);
    float r = v - __bfloat162float(h);
    __nv_bfloat16 l = __float2bfloat16(r);
    hi = *reinterpret_cast<uint16_t*>(&h);
    lo = *reinterpret_cast<uint16_t*>(&l);
}
__device__ __forceinline__ void cp16(uint32_t dst, const void* src) {
    asm volatile("cp.async.cg.shared.global [%0], [%1], 16;" :: "r"(dst), "l"(src));
}
__device__ __forceinline__ void cp_commit() {
    asm volatile("cp.async.commit_group;" ::: "memory");
}
template<int N>
__device__ __forceinline__ void cp_wait() {
    asm volatile("cp.async.wait_group %0;" :: "n"(N) : "memory");
}
__device__ __forceinline__ void ldsm4(uint32_t* r, uint32_t a) {
    asm volatile("ldmatrix.sync.aligned.m8n8.x4.shared.b16 {%0,%1,%2,%3}, [%4];"
        : "=r"(r[0]), "=r"(r[1]), "=r"(r[2]), "=r"(r[3]) : "r"(a));
}
__device__ __forceinline__ void mma16816(float* c, const uint32_t* a, uint32_t b0, uint32_t b1) {
    asm volatile("mma.sync.aligned.m16n8k16.row.col.f32.bf16.bf16.f32 "
        "{%0,%1,%2,%3},{%4,%5,%6,%7},{%8,%9},{%0,%1,%2,%3};"
        : "+f"(c[0]), "+f"(c[1]), "+f"(c[2]), "+f"(c[3])
        : "r"(a[0]), "r"(a[1]), "r"(a[2]), "r"(a[3]), "r"(b0), "r"(b1));
}

// ---------------- init ----------------
__global__ void init_kernel() {
    int i = threadIdx.x;
    if (i < NE) { g_count[i] = 0; g_cursor[i] = 0; }
    if (i == 0) g_aux = 0.f;
}

// ---------------- router ----------------
__global__ void router_kernel(const float* __restrict__ x,
                              const float* __restrict__ rw,
                              const float* __restrict__ rb) {
    int t = blockIdx.x;
    int tid = threadIdx.x;
    const float* xr = x + (size_t)t * DDIM;

    float acc[NE];
#pragma unroll
    for (int e = 0; e < NE; e++) acc[e] = 0.f;
    for (int d = tid; d < DDIM; d += 128) {
        float xv = xr[d];
#pragma unroll
        for (int e = 0; e < NE; e++) acc[e] += xv * rw[e * DDIM + d];
    }
    __shared__ float red[NE][128];
#pragma unroll
    for (int e = 0; e < NE; e++) red[e][tid] = acc[e];
    __syncthreads();
    for (int s = 64; s > 0; s >>= 1) {
        if (tid < s) {
#pragma unroll
            for (int e = 0; e < NE; e++) red[e][tid] += red[e][tid + s];
        }
        __syncthreads();
    }
    if (tid == 0) {
        float scores[NE];
        float aux = 0.f;
#pragma unroll
        for (int e = 0; e < NE; e++) {
            float l = red[e][0] + rb[e];
            aux += l * l;
            scores[e] = 1.f / (1.f + expf(-l));
        }
        atomicAdd(&g_aux, aux);
        int i0 = 0;
        for (int e = 1; e < NE; e++) if (scores[e] > scores[i0]) i0 = e;
        int i1 = -1;
        for (int e = 0; e < NE; e++) {
            if (e == i0) continue;
            if (i1 < 0 || scores[e] > scores[i1]) i1 = e;
        }
        float v0 = scores[i0], v1 = scores[i1];
        float inv = 1.f / (v0 + v1 + 1e-6f);
        g_topk_idx[t][0] = i0; g_topk_idx[t][1] = i1;
        g_topk_w[t][0] = v0 * inv; g_topk_w[t][1] = v1 * inv;
        atomicAdd(&g_count[i0], 1);
        atomicAdd(&g_count[i1], 1);
    }
}

// ---------------- scatter ----------------
__global__ void scatter_kernel() {
    int tid = threadIdx.x;
    if (tid == 0) {
        int o = 0;
        for (int e = 0; e < NE; e++) { g_offset[e] = o; o += g_count[e]; }
    }
    __syncthreads();
    for (int i = tid; i < NSLOT; i += 256) {
        int t = i >> 1, k = i & 1;
        int e = g_topk_idx[t][k];
        int pos = g_offset[e] + atomicAdd(&g_cursor[e], 1);
        g_slot_token[pos] = t;
        g_slot_of[t][k] = pos;
    }
}

// ---------------- gather + bf16 split of x ----------------
__global__ void gather_split_kernel(const float* __restrict__ x) {
    int idx = blockIdx.x * 256 + threadIdx.x;
    int s = idx >> 7;
    int c = (idx & 127) * 8;
    int t = g_slot_token[s];
    const float* xr = x + (size_t)t * DDIM + c;
    float4 a = *(const float4*)xr;
    float4 b = *(const float4*)(xr + 4);
    float v[8] = {a.x, a.y, a.z, a.w, b.x, b.y, b.z, b.w};
    uint16_t h[8], l[8];
#pragma unroll
    for (int i = 0; i < 8; i++) bf16_split(v[i], h[i], l[i]);
    uint4 hv = make_uint4((uint32_t)h[0] | ((uint32_t)h[1] << 16),
                          (uint32_t)h[2] | ((uint32_t)h[3] << 16),
                          (uint32_t)h[4] | ((uint32_t)h[5] << 16),
                          (uint32_t)h[6] | ((uint32_t)h[7] << 16));
    uint4 lv = make_uint4((uint32_t)l[0] | ((uint32_t)l[1] << 16),
                          (uint32_t)l[2] | ((uint32_t)l[3] << 16),
                          (uint32_t)l[4] | ((uint32_t)l[5] << 16),
                          (uint32_t)l[6] | ((uint32_t)l[7] << 16));
    *(uint4*)&g_xg_hi[(size_t)s * DDIM + c] = hv;
    *(uint4*)&g_xg_lo[(size_t)s * DDIM + c] = lv;
}

// ---------------- transpose + bf16 split of weights ----------------
template<int MODE>
__global__ void transpose_split_kernel(const float* __restrict__ in) {
    constexpr int Kd = (MODE == 0) ? DDIM : HDIM;
    constexpr int Nd = (MODE == 0) ? H2 : DDIM;
    uint16_t* ohi = (MODE == 0) ? g_w12t_hi : g_w3t_hi;
    uint16_t* olo = (MODE == 0) ? g_w12t_lo : g_w3t_lo;

    __shared__ float tbuf[32][33];
    int e = blockIdx.z;
    const float* src = in + (size_t)e * Kd * Nd;
    uint16_t* dhi = ohi + (size_t)e * Kd * Nd;
    uint16_t* dlo = olo + (size_t)e * Kd * Nd;

    int n = blockIdx.x * 32 + threadIdx.x;
    int k0 = blockIdx.y * 32;
#pragma unroll
    for (int j = 0; j < 32; j += 8)
        tbuf[threadIdx.y + j][threadIdx.x] = src[(size_t)(k0 + threadIdx.y + j) * Nd + n];
    __syncthreads();
    int k = k0 + threadIdx.x;
    int nb = blockIdx.x * 32;
#pragma unroll
    for (int j = 0; j < 32; j += 8) {
        float v = tbuf[threadIdx.x][threadIdx.y + j];
        uint16_t h, l;
        bf16_split(v, h, l);
        size_t o = (size_t)(nb + threadIdx.y + j) * Kd + k;
        dhi[o] = h; dlo[o] = l;
    }
}

// ---------------- grouped GEMM via mma.sync, split-bf16 3-term ----------
// 512 threads, 16 warps, CTA tile 128x128, warp tile 64x16, KC=64, 3 stages.
// MODE 0: A = g_xg [slot,DDIM], B = g_w12t (64 h1 + 64 h2 rows), SwiGLU epi
// MODE 1: A = g_hid [slot,HDIM], B = g_w3t, C = g_y [slot,DDIM]
template<int MODE>
__global__ void __launch_bounds__(GTHREADS, 1) moe_gemm_mma() {
    constexpr int KDIM = (MODE == 0) ? DDIM : HDIM;
    constexpr int NTOT = (MODE == 0) ? H2 : DDIM;
    constexpr int NC = KDIM / KC;
    const uint16_t* Ahi = (MODE == 0) ? g_xg_hi : g_hid_hi;
    const uint16_t* Alo = (MODE == 0) ? g_xg_lo : g_hid_lo;

    const int e = blockIdx.z;
    const int cnt = g_count[e];
    const int row0 = blockIdx.y * 128;
    if (row0 >= cnt) return;
    const int off = g_offset[e];
    const int n0 = (MODE == 0) ? blockIdx.x * 64 : blockIdx.x * 128;
    const uint16_t* Bhi = ((MODE == 0) ? g_w12t_hi : g_w3t_hi) + (size_t)e * NTOT * KDIM;
    const uint16_t* Blo = ((MODE == 0) ? g_w12t_lo : g_w3t_lo) + (size_t)e * NTOT * KDIM;

    extern __shared__ __align__(128) char smem[];
    const uint32_t sb = smem_u32(smem);
    const int tid = threadIdx.x;
    const int lane = tid & 31;
    const int wid = tid >> 5;              // 0..15
    const int wm = (wid & 1) * 64;         // warp m-offset
    const int wn = (wid >> 1) * 16;        // warp n-offset (16 cols)

    // --- per-thread cp.async tasks: 2 (row,chunk) units, 4 tiles each ---
    uint32_t dsto[2];
    size_t   asrc[2], bsrc[2];
#pragma unroll
    for (int q = 0; q < 2; q++) {
        int u = tid + q * GTHREADS;
        int r = u >> 3, cs = u & 7;
        dsto[q] = (uint32_t)(r * 128 + ((cs ^ (r & 7)) << 4));
        int ar = row0 + r; if (ar >= cnt) ar = cnt - 1;
        asrc[q] = (size_t)(off + ar) * KDIM + cs * 8;
        int ne;
        if (MODE == 0) ne = (r < 64) ? (n0 + r) : (HDIM + n0 + r - 64);
        else           ne = n0 + r;
        bsrc[q] = (size_t)ne * KDIM + cs * 8;
    }

    auto issue = [&](int c) {
        uint32_t st = sb + (c % 3) * STAGE_BYTES;
        int k0 = c * KC;
#pragma unroll
        for (int q = 0; q < 2; q++) {
            cp16(st + OFF_AHI + dsto[q], Ahi + asrc[q] + k0);
            cp16(st + OFF_ALO + dsto[q], Alo + asrc[q] + k0);
            cp16(st + OFF_BHI + dsto[q], Bhi + bsrc[q] + k0);
            cp16(st + OFF_BLO + dsto[q], Blo + bsrc[q] + k0);
        }
        cp_commit();
    };

    float acc[4][2][4];
#pragma unroll
    for (int i = 0; i < 4; i++)
#pragma unroll
        for (int j = 0; j < 2; j++)
#pragma unroll
            for (int q = 0; q < 4; q++) acc[i][j][q] = 0.f;

    // ldmatrix row precompute
    const int lane15 = lane & 15, laneh = lane >> 4;
    uint32_t rA128[4];
    int rA7[4];
#pragma unroll
    for (int i = 0; i < 4; i++) {
        int r = wm + i * 16 + lane15;
        rA128[i] = r * 128; rA7[i] = r & 7;
    }
    const uint32_t rB128 = (wn + lane15) * 128;
    const int rB7 = (wn + lane15) & 7;

    issue(0);
    if (NC > 1) issue(1);

    for (int c = 0; c < NC; ++c) {
        if (c + 2 < NC) { cp_wait<1>(); } else { cp_wait<0>(); }
        __syncthreads();
        if (c + 2 < NC) issue(c + 2);

        uint32_t S = sb + (c % 3) * STAGE_BYTES;
#pragma unroll
        for (int kh = 0; kh < 4; kh++) {
            int cc = kh * 2 + laneh;
            uint32_t ah[4][4], al[4][4], bh[4], bl[4];
#pragma unroll
            for (int i = 0; i < 4; i++) {
                uint32_t o = rA128[i] + (uint32_t)((cc ^ rA7[i]) << 4);
                ldsm4(ah[i], S + OFF_AHI + o);
                ldsm4(al[i], S + OFF_ALO + o);
            }
            {
                uint32_t o = rB128 + (uint32_t)((cc ^ rB7) << 4);
                ldsm4(bh, S + OFF_BHI + o);
                ldsm4(bl, S + OFF_BLO + o);
            }
#pragma unroll
            for (int i = 0; i < 4; i++)
#pragma unroll
                for (int j = 0; j < 2; j++) {
                    mma16816(acc[i][j], ah[i], bh[j], bh[j + 2]);   // hi*hi
                    mma16816(acc[i][j], ah[i], bl[j], bl[j + 2]);   // hi*lo
                    mma16816(acc[i][j], al[i], bh[j], bh[j + 2]);   // lo*hi
                }
        }
        __syncthreads();
    }

    const int rows_valid = (cnt - row0 < 128) ? (cnt - row0) : 128;

    if (MODE == 0) {
        // stage acc to smem, fuse SwiGLU: cols 0-63 = h1, 64-127 = h2
        float* ebuf = (float*)smem;   // pitch 132 floats, 128 rows
#pragma unroll
        for (int i = 0; i < 4; i++) {
            int r_lo = wm + i * 16 + (lane >> 2);
            int r_hi = r_lo + 8;
#pragma unroll
            for (int j = 0; j < 2; j++) {
                int col = wn + j * 8 + (lane & 3) * 2;
                *(float2*)&ebuf[r_lo * 132 + col] = make_float2(acc[i][j][0], acc[i][j][1]);
                *(float2*)&ebuf[r_hi * 132 + col] = make_float2(acc[i][j][2], acc[i][j][3]);
            }
        }
        __syncthreads();
#pragma unroll
        for (int it = 0; it < 8; it++) {
            int idx = tid + it * GTHREADS;      // 4096 col-pairs
            int row = idx >> 5;
            int cp = (idx & 31) * 2;
            if (row < rows_valid) {
                float h1a = ebuf[row * 132 + cp];
                float h1b = ebuf[row * 132 + cp + 1];
                float h2a = ebuf[row * 132 + 64 + cp];
                float h2b = ebuf[row * 132 + 64 + cp + 1];
                float oa = (h1a / (1.f + expf(-h1a))) * h2a;
                float ob = (h1b / (1.f + expf(-h1b))) * h2b;
                uint16_t ha, la, hb, lb;
                bf16_split(oa, ha, la);
                bf16_split(ob, hb, lb);
                size_t go = (size_t)(off + row0 + row) * HDIM + n0 + cp;
                *(uint32_t*)&g_hid_hi[go] = (uint32_t)ha | ((uint32_t)hb << 16);
                *(uint32_t*)&g_hid_lo[go] = (uint32_t)la | ((uint32_t)lb << 16);
            }
        }
    } else {
        float* Out = g_y;
#pragma unroll
        for (int i = 0; i < 4; i++) {
            int r_lo = wm + i * 16 + (lane >> 2);
            int r_hi = r_lo + 8;
#pragma unroll
            for (int j = 0; j < 2; j++) {
                int col = n0 + wn + j * 8 + (lane & 3) * 2;
                if (r_lo < rows_valid)
                    *(float2*)&Out[(size_t)(off + row0 + r_lo) * NTOT + col] =
                        make_float2(acc[i][j][0], acc[i][j][1]);
                if (r_hi < rows_valid)
                    *(float2*)&Out[(size_t)(off + row0 + r_hi) * NTOT + col] =
                        make_float2(acc[i][j][2], acc[i][j][3]);
            }
        }
    }
}

// ---------------- combine ----------------
__global__ void combine_kernel(float* __restrict__ out, int out_size) {
    size_t gid = (size_t)blockIdx.x * blockDim.x + threadIdx.x;
    size_t idx = gid * 4;
    if (idx < (size_t)TT * DDIM) {
        int t = (int)(idx / DDIM);
        int d = (int)(idx % DDIM);
        int s0 = g_slot_of[t][0], s1 = g_slot_of[t][1];
        float w0 = g_topk_w[t][0], w1 = g_topk_w[t][1];
        float4 y0 = *(const float4*)&g_y[(size_t)s0 * DDIM + d];
        float4 y1 = *(const float4*)&g_y[(size_t)s1 * DDIM + d];
        float4 o;
        o.x = w0 * y0.x + w1 * y1.x;
        o.y = w0 * y0.y + w1 * y1.y;
        o.z = w0 * y0.z + w1 * y1.z;
        o.w = w0 * y0.w + w1 * y1.w;
        *(float4*)&out[idx] = o;
    }
    if (gid == 0 && out_size > TT * DDIM) {
        out[TT * DDIM] = 0.01f * g_aux / (float)(TT * NE);
    }
}

// ---------------- launch ----------------
extern "C" void kernel_launch(void* const* d_in, const int* in_sizes, int n_in,
                              void* d_out, int out_size) {
    const float* x   = (const float*)d_in[0];
    const float* rw  = (const float*)d_in[1];
    const float* rb  = (const float*)d_in[2];
    const float* w12 = (const float*)d_in[3];
    const float* w3  = (const float*)d_in[4];
    float* out = (float*)d_out;

    cudaFuncSetAttribute(moe_gemm_mma<0>, cudaFuncAttributeMaxDynamicSharedMemorySize, GEMM_SMEM);
    cudaFuncSetAttribute(moe_gemm_mma<1>, cudaFuncAttributeMaxDynamicSharedMemorySize, GEMM_SMEM);

    init_kernel<<<1, 32>>>();
    router_kernel<<<TT, 128>>>(x, rw, rb);
    scatter_kernel<<<1, 256>>>();
    gather_split_kernel<<<(NSLOT * DDIM / 8) / 256, 256>>>(x);
    transpose_split_kernel<0><<<dim3(H2 / 32, DDIM / 32, NE), dim3(32, 8)>>>(w12);
    transpose_split_kernel<1><<<dim3(DDIM / 32, HDIM / 32, NE), dim3(32, 8)>>>(w3);
    moe_gemm_mma<0><<<dim3(HDIM / 64, NSLOT / 128, NE), GTHREADS, GEMM_SMEM>>>();
    moe_gemm_mma<1><<<dim3(DDIM / 128, NSLOT / 128, NE), GTHREADS, GEMM_SMEM>>>();
    combine_kernel<<<(TT * DDIM / 4) / 256, 256>>>(out, out_size);
}

// round 6
// speedup vs baseline: 2.5532x; 1.0074x over previous
#include <cuda_runtime.h>
#include <cuda_bf16.h>
#include <math.h>
#include <stdint.h>

// Problem constants
#define TT    2048
#define DDIM  1024
#define HDIM  2048
#define H2    4096
#define NE    8
#define NK    2
#define NSLOT 4096

// GEMM tile config
#define KC     64                     // k elements per chunk (=128B row)
#define OFF_AHI 0
#define OFF_ALO 16384
#define OFF_BHI 32768
#define OFF_BLO 49152
#define STAGE_BYTES 65536
#define GEMM_SMEM   (3 * STAGE_BYTES) // 196608
#define GTHREADS 512

// ---------------- device scratch ----------------
__device__ __align__(256) float    g_y[(size_t)NSLOT * DDIM];
__device__ __align__(256) uint16_t g_xg_hi[(size_t)NSLOT * DDIM];
__device__ __align__(256) uint16_t g_xg_lo[(size_t)NSLOT * DDIM];
__device__ __align__(256) uint16_t g_hid_hi[(size_t)NSLOT * HDIM];
__device__ __align__(256) uint16_t g_hid_lo[(size_t)NSLOT * HDIM];
__device__ __align__(256) uint16_t g_w12t_hi[(size_t)NE * H2 * DDIM];
__device__ __align__(256) uint16_t g_w12t_lo[(size_t)NE * H2 * DDIM];
__device__ __align__(256) uint16_t g_w3t_hi[(size_t)NE * DDIM * HDIM];
__device__ __align__(256) uint16_t g_w3t_lo[(size_t)NE * DDIM * HDIM];
__device__ int   g_topk_idx[TT][NK];
__device__ float g_topk_w[TT][NK];
__device__ int   g_count[NE];
__device__ int   g_offset[NE];
__device__ int   g_cursor[NE];
__device__ int   g_slot_token[NSLOT];
__device__ int   g_slot_of[TT][NK];
__device__ float g_aux;

// ---------------- helpers ----------------
__device__ __forceinline__ uint32_t smem_u32(const void* p) {
    return (uint32_t)__cvta_generic_to_shared(p);
}
__device__ __forceinline__ void bf16_split(float v, uint16_t& hi, uint16_t& lo) {
    __nv_bfloat16 h = __float2bfloat16(v);
    float r = v - __bfloat162float(h);
    __nv_bfloat16 l = __float2bfloat16(r);
    hi = *reinterpret_cast<uint16_t*>(&h);
    lo = *reinterpret_cast<uint16_t*>(&l);
}
__device__ __forceinline__ void cp16(uint32_t dst, const void* src) {
    asm volatile("cp.async.cg.shared.global [%0], [%1], 16;" :: "r"(dst), "l"(src));
}
__device__ __forceinline__ void cp_commit() {
    asm volatile("cp.async.commit_group;" ::: "memory");
}
template<int N>
__device__ __forceinline__ void cp_wait() {
    asm volatile("cp.async.wait_group %0;" :: "n"(N) : "memory");
}
__device__ __forceinline__ void ldsm4(uint32_t* r, uint32_t a) {
    asm volatile("ldmatrix.sync.aligned.m8n8.x4.shared.b16 {%0,%1,%2,%3}, [%4];"
        : "=r"(r[0]), "=r"(r[1]), "=r"(r[2]), "=r"(r[3]) : "r"(a));
}
__device__ __forceinline__ void mma16816(float* c, const uint32_t* a, uint32_t b0, uint32_t b1) {
    asm volatile("mma.sync.aligned.m16n8k16.row.col.f32.bf16.bf16.f32 "
        "{%0,%1,%2,%3},{%4,%5,%6,%7},{%8,%9},{%0,%1,%2,%3};"
        : "+f"(c[0]), "+f"(c[1]), "+f"(c[2]), "+f"(c[3])
        : "r"(a[0]), "r"(a[1]), "r"(a[2]), "r"(a[3]), "r"(b0), "r"(b1));
}

// ---------------- init ----------------
__global__ void init_kernel() {
    int i = threadIdx.x;
    if (i < NE) { g_count[i] = 0; g_cursor[i] = 0; }
    if (i == 0) g_aux = 0.f;
}

// ---------------- router ----------------
__global__ void router_kernel(const float* __restrict__ x,
                              const float* __restrict__ rw,
                              const float* __restrict__ rb) {
    int t = blockIdx.x;
    int tid = threadIdx.x;
    const float* xr = x + (size_t)t * DDIM;

    float acc[NE];
#pragma unroll
    for (int e = 0; e < NE; e++) acc[e] = 0.f;
    for (int d = tid; d < DDIM; d += 128) {
        float xv = xr[d];
#pragma unroll
        for (int e = 0; e < NE; e++) acc[e] += xv * rw[e * DDIM + d];
    }
    __shared__ float red[NE][128];
#pragma unroll
    for (int e = 0; e < NE; e++) red[e][tid] = acc[e];
    __syncthreads();
    for (int s = 64; s > 0; s >>= 1) {
        if (tid < s) {
#pragma unroll
            for (int e = 0; e < NE; e++) red[e][tid] += red[e][tid + s];
        }
        __syncthreads();
    }
    if (tid == 0) {
        float scores[NE];
        float aux = 0.f;
#pragma unroll
        for (int e = 0; e < NE; e++) {
            float l = red[e][0] + rb[e];
            aux += l * l;
            scores[e] = 1.f / (1.f + expf(-l));
        }
        atomicAdd(&g_aux, aux);
        int i0 = 0;
        for (int e = 1; e < NE; e++) if (scores[e] > scores[i0]) i0 = e;
        int i1 = -1;
        for (int e = 0; e < NE; e++) {
            if (e == i0) continue;
            if (i1 < 0 || scores[e] > scores[i1]) i1 = e;
        }
        float v0 = scores[i0], v1 = scores[i1];
        float inv = 1.f / (v0 + v1 + 1e-6f);
        g_topk_idx[t][0] = i0; g_topk_idx[t][1] = i1;
        g_topk_w[t][0] = v0 * inv; g_topk_w[t][1] = v1 * inv;
        atomicAdd(&g_count[i0], 1);
        atomicAdd(&g_count[i1], 1);
    }
}

// ---------------- scatter ----------------
__global__ void scatter_kernel() {
    int tid = threadIdx.x;
    if (tid == 0) {
        int o = 0;
        for (int e = 0; e < NE; e++) { g_offset[e] = o; o += g_count[e]; }
    }
    __syncthreads();
    for (int i = tid; i < NSLOT; i += 256) {
        int t = i >> 1, k = i & 1;
        int e = g_topk_idx[t][k];
        int pos = g_offset[e] + atomicAdd(&g_cursor[e], 1);
        g_slot_token[pos] = t;
        g_slot_of[t][k] = pos;
    }
}

// ---------------- gather + bf16 split of x ----------------
__global__ void gather_split_kernel(const float* __restrict__ x) {
    int idx = blockIdx.x * 256 + threadIdx.x;
    int s = idx >> 7;
    int c = (idx & 127) * 8;
    int t = g_slot_token[s];
    const float* xr = x + (size_t)t * DDIM + c;
    float4 a = *(const float4*)xr;
    float4 b = *(const float4*)(xr + 4);
    float v[8] = {a.x, a.y, a.z, a.w, b.x, b.y, b.z, b.w};
    uint16_t h[8], l[8];
#pragma unroll
    for (int i = 0; i < 8; i++) bf16_split(v[i], h[i], l[i]);
    uint4 hv = make_uint4((uint32_t)h[0] | ((uint32_t)h[1] << 16),
                          (uint32_t)h[2] | ((uint32_t)h[3] << 16),
                          (uint32_t)h[4] | ((uint32_t)h[5] << 16),
                          (uint32_t)h[6] | ((uint32_t)h[7] << 16));
    uint4 lv = make_uint4((uint32_t)l[0] | ((uint32_t)l[1] << 16),
                          (uint32_t)l[2] | ((uint32_t)l[3] << 16),
                          (uint32_t)l[4] | ((uint32_t)l[5] << 16),
                          (uint32_t)l[6] | ((uint32_t)l[7] << 16));
    *(uint4*)&g_xg_hi[(size_t)s * DDIM + c] = hv;
    *(uint4*)&g_xg_lo[(size_t)s * DDIM + c] = lv;
}

// ---------------- transpose + bf16 split of weights (vectorized) ----------
// block (16,16): load 32x32 fp32 tile with float2, store uint32 (2xbf16) pairs
template<int MODE>
__global__ void transpose_split_kernel(const float* __restrict__ in) {
    constexpr int Kd = (MODE == 0) ? DDIM : HDIM;
    constexpr int Nd = (MODE == 0) ? H2 : DDIM;
    uint16_t* ohi = (MODE == 0) ? g_w12t_hi : g_w3t_hi;
    uint16_t* olo = (MODE == 0) ? g_w12t_lo : g_w3t_lo;

    __shared__ float tbuf[32][33];
    const int e = blockIdx.z;
    const int tx = threadIdx.x;     // 0..15
    const int ty = threadIdx.y;     // 0..15
    const int k0 = blockIdx.y * 32;
    const int nb = blockIdx.x * 32;
    const float* src = in + (size_t)e * Kd * Nd + (size_t)k0 * Nd + nb;
    uint16_t* dhi = ohi + (size_t)e * Kd * Nd;
    uint16_t* dlo = olo + (size_t)e * Kd * Nd;

#pragma unroll
    for (int j = 0; j < 32; j += 16) {
        float2 v = *(const float2*)(src + (size_t)(ty + j) * Nd + tx * 2);
        tbuf[ty + j][tx * 2] = v.x;
        tbuf[ty + j][tx * 2 + 1] = v.y;
    }
    __syncthreads();

    const int k = k0 + tx * 2;
#pragma unroll
    for (int j = 0; j < 32; j += 16) {
        int n = ty + j;
        float v0 = tbuf[tx * 2][n];
        float v1 = tbuf[tx * 2 + 1][n];
        uint16_t h0, l0, h1, l1;
        bf16_split(v0, h0, l0);
        bf16_split(v1, h1, l1);
        size_t o = (size_t)(nb + n) * Kd + k;
        *(uint32_t*)&dhi[o] = (uint32_t)h0 | ((uint32_t)h1 << 16);
        *(uint32_t*)&dlo[o] = (uint32_t)l0 | ((uint32_t)l1 << 16);
    }
}

// ---------------- grouped GEMM via mma.sync, split-bf16 3-term ----------
// 512 threads, 16 warps, CTA tile 128x128, warp tile 64x16, KC=64, 3 stages.
// Ragged-tile skip: warps skip A-fragments whose rows are beyond rows_valid.
// MODE 0: A = g_xg [slot,DDIM], B = g_w12t (64 h1 + 64 h2 rows), SwiGLU epi
// MODE 1: A = g_hid [slot,HDIM], B = g_w3t, C = g_y [slot,DDIM]
template<int MODE>
__global__ void __launch_bounds__(GTHREADS, 1) moe_gemm_mma() {
    constexpr int KDIM = (MODE == 0) ? DDIM : HDIM;
    constexpr int NTOT = (MODE == 0) ? H2 : DDIM;
    constexpr int NC = KDIM / KC;
    const uint16_t* Ahi = (MODE == 0) ? g_xg_hi : g_hid_hi;
    const uint16_t* Alo = (MODE == 0) ? g_xg_lo : g_hid_lo;

    const int e = blockIdx.z;
    const int cnt = g_count[e];
    const int row0 = blockIdx.y * 128;
    if (row0 >= cnt) return;
    const int off = g_offset[e];
    const int n0 = (MODE == 0) ? blockIdx.x * 64 : blockIdx.x * 128;
    const uint16_t* Bhi = ((MODE == 0) ? g_w12t_hi : g_w3t_hi) + (size_t)e * NTOT * KDIM;
    const uint16_t* Blo = ((MODE == 0) ? g_w12t_lo : g_w3t_lo) + (size_t)e * NTOT * KDIM;

    extern __shared__ __align__(128) char smem[];
    const uint32_t sb = smem_u32(smem);
    const int tid = threadIdx.x;
    const int lane = tid & 31;
    const int wid = tid >> 5;              // 0..15
    const int wm = (wid & 1) * 64;         // warp m-offset
    const int wn = (wid >> 1) * 16;        // warp n-offset (16 cols)
    const int rows_valid = (cnt - row0 < 128) ? (cnt - row0) : 128;

    // --- per-thread cp.async tasks: 2 (row,chunk) units, 4 tiles each ---
    uint32_t dsto[2];
    size_t   asrc[2], bsrc[2];
#pragma unroll
    for (int q = 0; q < 2; q++) {
        int u = tid + q * GTHREADS;
        int r = u >> 3, cs = u & 7;
        dsto[q] = (uint32_t)(r * 128 + ((cs ^ (r & 7)) << 4));
        int ar = row0 + r; if (ar >= cnt) ar = cnt - 1;
        asrc[q] = (size_t)(off + ar) * KDIM + cs * 8;
        int ne;
        if (MODE == 0) ne = (r < 64) ? (n0 + r) : (HDIM + n0 + r - 64);
        else           ne = n0 + r;
        bsrc[q] = (size_t)ne * KDIM + cs * 8;
    }

    auto issue = [&](int c) {
        uint32_t st = sb + (c % 3) * STAGE_BYTES;
        int k0 = c * KC;
#pragma unroll
        for (int q = 0; q < 2; q++) {
            cp16(st + OFF_AHI + dsto[q], Ahi + asrc[q] + k0);
            cp16(st + OFF_ALO + dsto[q], Alo + asrc[q] + k0);
            cp16(st + OFF_BHI + dsto[q], Bhi + bsrc[q] + k0);
            cp16(st + OFF_BLO + dsto[q], Blo + bsrc[q] + k0);
        }
        cp_commit();
    };

    float acc[4][2][4];
#pragma unroll
    for (int i = 0; i < 4; i++)
#pragma unroll
        for (int j = 0; j < 2; j++)
#pragma unroll
            for (int q = 0; q < 4; q++) acc[i][j][q] = 0.f;

    // ldmatrix row precompute
    const int lane15 = lane & 15, laneh = lane >> 4;
    uint32_t rA128[4];
    int rA7[4];
#pragma unroll
    for (int i = 0; i < 4; i++) {
        int r = wm + i * 16 + lane15;
        rA128[i] = r * 128; rA7[i] = r & 7;
    }
    const uint32_t rB128 = (wn + lane15) * 128;
    const int rB7 = (wn + lane15) & 7;

    issue(0);
    if (NC > 1) issue(1);

    for (int c = 0; c < NC; ++c) {
        if (c + 2 < NC) { cp_wait<1>(); } else { cp_wait<0>(); }
        __syncthreads();
        if (c + 2 < NC) issue(c + 2);

        uint32_t S = sb + (c % 3) * STAGE_BYTES;
#pragma unroll
        for (int kh = 0; kh < 4; kh++) {
            int cc = kh * 2 + laneh;
            uint32_t bh[4], bl[4];
            {
                uint32_t o = rB128 + (uint32_t)((cc ^ rB7) << 4);
                ldsm4(bh, S + OFF_BHI + o);
                ldsm4(bl, S + OFF_BLO + o);
            }
#pragma unroll
            for (int i = 0; i < 4; i++) {
                if (wm + i * 16 < rows_valid) {     // warp-uniform ragged skip
                    uint32_t ah[4], al[4];
                    uint32_t o = rA128[i] + (uint32_t)((cc ^ rA7[i]) << 4);
                    ldsm4(ah, S + OFF_AHI + o);
                    ldsm4(al, S + OFF_ALO + o);
#pragma unroll
                    for (int j = 0; j < 2; j++) {
                        mma16816(acc[i][j], ah, bh[j], bh[j + 2]);   // hi*hi
                        mma16816(acc[i][j], ah, bl[j], bl[j + 2]);   // hi*lo
                        mma16816(acc[i][j], al, bh[j], bh[j + 2]);   // lo*hi
                    }
                }
            }
        }
        // no trailing sync: 3-stage ring + top-of-loop barrier orders reuse
    }

    __syncthreads();   // protect smem reuse by epilogue

    if (MODE == 0) {
        // stage acc to smem, fuse SwiGLU: cols 0-63 = h1, 64-127 = h2
        float* ebuf = (float*)smem;   // pitch 132 floats, 128 rows
#pragma unroll
        for (int i = 0; i < 4; i++) {
            int r_lo = wm + i * 16 + (lane >> 2);
            int r_hi = r_lo + 8;
#pragma unroll
            for (int j = 0; j < 2; j++) {
                int col = wn + j * 8 + (lane & 3) * 2;
                *(float2*)&ebuf[r_lo * 132 + col] = make_float2(acc[i][j][0], acc[i][j][1]);
                *(float2*)&ebuf[r_hi * 132 + col] = make_float2(acc[i][j][2], acc[i][j][3]);
            }
        }
        __syncthreads();
#pragma unroll
        for (int it = 0; it < 8; it++) {
            int idx = tid + it * GTHREADS;      // 4096 col-pairs
            int row = idx >> 5;
            int cp = (idx & 31) * 2;
            if (row < rows_valid) {
                float h1a = ebuf[row * 132 + cp];
                float h1b = ebuf[row * 132 + cp + 1];
                float h2a = ebuf[row * 132 + 64 + cp];
                float h2b = ebuf[row * 132 + 64 + cp + 1];
                float oa = (h1a / (1.f + expf(-h1a))) * h2a;
                float ob = (h1b / (1.f + expf(-h1b))) * h2b;
                uint16_t ha, la, hb, lb;
                bf16_split(oa, ha, la);
                bf16_split(ob, hb, lb);
                size_t go = (size_t)(off + row0 + row) * HDIM + n0 + cp;
                *(uint32_t*)&g_hid_hi[go] = (uint32_t)ha | ((uint32_t)hb << 16);
                *(uint32_t*)&g_hid_lo[go] = (uint32_t)la | ((uint32_t)lb << 16);
            }
        }
    } else {
        float* Out = g_y;
#pragma unroll
        for (int i = 0; i < 4; i++) {
            int r_lo = wm + i * 16 + (lane >> 2);
            int r_hi = r_lo + 8;
#pragma unroll
            for (int j = 0; j < 2; j++) {
                int col = n0 + wn + j * 8 + (lane & 3) * 2;
                if (r_lo < rows_valid)
                    *(float2*)&Out[(size_t)(off + row0 + r_lo) * NTOT + col] =
                        make_float2(acc[i][j][0], acc[i][j][1]);
                if (r_hi < rows_valid)
                    *(float2*)&Out[(size_t)(off + row0 + r_hi) * NTOT + col] =
                        make_float2(acc[i][j][2], acc[i][j][3]);
            }
        }
    }
}

// ---------------- combine ----------------
__global__ void combine_kernel(float* __restrict__ out, int out_size) {
    size_t gid = (size_t)blockIdx.x * blockDim.x + threadIdx.x;
    size_t idx = gid * 4;
    if (idx < (size_t)TT * DDIM) {
        int t = (int)(idx / DDIM);
        int d = (int)(idx % DDIM);
        int s0 = g_slot_of[t][0], s1 = g_slot_of[t][1];
        float w0 = g_topk_w[t][0], w1 = g_topk_w[t][1];
        float4 y0 = *(const float4*)&g_y[(size_t)s0 * DDIM + d];
        float4 y1 = *(const float4*)&g_y[(size_t)s1 * DDIM + d];
        float4 o;
        o.x = w0 * y0.x + w1 * y1.x;
        o.y = w0 * y0.y + w1 * y1.y;
        o.z = w0 * y0.z + w1 * y1.z;
        o.w = w0 * y0.w + w1 * y1.w;
        *(float4*)&out[idx] = o;
    }
    if (gid == 0 && out_size > TT * DDIM) {
        out[TT * DDIM] = 0.01f * g_aux / (float)(TT * NE);
    }
}

// ---------------- launch ----------------
extern "C" void kernel_launch(void* const* d_in, const int* in_sizes, int n_in,
                              void* d_out, int out_size) {
    const float* x   = (const float*)d_in[0];
    const float* rw  = (const float*)d_in[1];
    const float* rb  = (const float*)d_in[2];
    const float* w12 = (const float*)d_in[3];
    const float* w3  = (const float*)d_in[4];
    float* out = (float*)d_out;

    cudaFuncSetAttribute(moe_gemm_mma<0>, cudaFuncAttributeMaxDynamicSharedMemorySize, GEMM_SMEM);
    cudaFuncSetAttribute(moe_gemm_mma<1>, cudaFuncAttributeMaxDynamicSharedMemorySize, GEMM_SMEM);

    init_kernel<<<1, 32>>>();
    router_kernel<<<TT, 128>>>(x, rw, rb);
    scatter_kernel<<<1, 256>>>();
    gather_split_kernel<<<(NSLOT * DDIM / 8) / 256, 256>>>(x);
    transpose_split_kernel<0><<<dim3(H2 / 32, DDIM / 32, NE), dim3(16, 16)>>>(w12);
    transpose_split_kernel<1><<<dim3(DDIM / 32, HDIM / 32, NE), dim3(16, 16)>>>(w3);
    moe_gemm_mma<0><<<dim3(HDIM / 64, NSLOT / 128, NE), GTHREADS, GEMM_SMEM>>>();
    moe_gemm_mma<1><<<dim3(DDIM / 128, NSLOT / 128, NE), GTHREADS, GEMM_SMEM>>>();
    combine_kernel<<<(TT * DDIM / 4) / 256, 256>>>(out, out_size);
}